// round 4
// baseline (speedup 1.0000x reference)
#include <cuda_runtime.h>
#include <math.h>
#include <stdint.h>

// Problem constants
#define NN   10000
#define EE   150000
#define FF0  128
#define HH   8
#define DD   64
#define HD   512
#define GG   64
#define CC   10
#define XCW  2048          // 4*HD concat width
#define ECAP 96            // cached incoming-edge capacity per node (avg deg = 15)

// ---------------- device scratch (no allocations allowed) ----------------
__device__ float g_h [(size_t)NN*HD];
__device__ float g_x0[(size_t)NN*HD];
__device__ float g_x3[(size_t)NN*HD];
__device__ float g_xc[(size_t)NN*XCW];
__device__ float g_es[(size_t)NN*HH];
__device__ float g_ed[(size_t)NN*HH];
__device__ float g_pool[GG*XCW];
__device__ float g_z  [GG*HD];
__device__ int   g_cnt[NN];
__device__ int   g_cur[NN];
__device__ int   g_rowptr[NN+1];
__device__ int   g_csr[EE];
__device__ int   g_goff[GG+1];

// ---------------- small utility kernels ----------------
__global__ void fill_int_kernel(int* p, int v, int n) {
    int i = blockIdx.x * blockDim.x + threadIdx.x;
    if (i < n) p[i] = v;
}

__global__ void hist_kernel(const int* __restrict__ dst, int* __restrict__ cnt) {
    int i = blockIdx.x * blockDim.x + threadIdx.x;
    if (i < EE) atomicAdd(&cnt[dst[i]], 1);
}

// single block, 1024 threads, 10 elements each -> exclusive scan of cnt into rowptr
__global__ void scan_kernel(const int* __restrict__ cnt, int* __restrict__ rowptr) {
    __shared__ int sums[1024];
    int t = threadIdx.x;
    int base = t * 10;
    int loc[10];
    int s = 0;
#pragma unroll
    for (int i = 0; i < 10; i++) {
        loc[i] = s;
        int idx = base + i;
        s += (idx < NN) ? cnt[idx] : 0;
    }
    int tot = s;
    sums[t] = s;
    __syncthreads();
    for (int off = 1; off < 1024; off <<= 1) {
        int v = (t >= off) ? sums[t - off] : 0;
        __syncthreads();
        sums[t] += v;
        __syncthreads();
    }
    int excl = sums[t] - tot;
#pragma unroll
    for (int i = 0; i < 10; i++) {
        int idx = base + i;
        if (idx < NN) rowptr[idx] = excl + loc[i];
    }
    if (t == 1023) rowptr[NN] = sums[1023];
}

__global__ void scatter_kernel(const int* __restrict__ src, const int* __restrict__ dst,
                               const int* __restrict__ rowptr, int* __restrict__ cur,
                               int* __restrict__ csr) {
    int i = blockIdx.x * blockDim.x + threadIdx.x;
    if (i >= EE) return;
    int d = dst[i];
    int pos = atomicAdd(&cur[d], 1);
    csr[rowptr[d] + pos] = src[i];
}

__global__ void goff_min_kernel(const int* __restrict__ batch, int* __restrict__ goff) {
    int i = blockIdx.x * blockDim.x + threadIdx.x;
    if (i < NN) atomicMin(&goff[batch[i]], i);
}

__global__ void goff_fix_kernel(int* goff) {
    goff[GG] = NN;
    for (int g = GG - 1; g >= 0; g--)
        if (goff[g] > goff[g + 1]) goff[g] = goff[g + 1];
}

// ---------------- SGEMM: C[M,512] = A[M,K](lda) @ B[K,512] ----------------
// BM=128 BN=128 BK=16, 256 threads, 8x8 microtile
__global__ __launch_bounds__(256)
void sgemm_kernel(const float* __restrict__ A, int lda,
                  const float* __restrict__ B,
                  float* __restrict__ C, int M, int K) {
    __shared__ float As[16][128];
    __shared__ float Bs[16][128];
    const int bx = blockIdx.x;   // col block (0..3)
    const int by = blockIdx.y;   // row block
    const int tid = threadIdx.x;
    const int tr = tid >> 4;     // 0..15
    const int tc = tid & 15;     // 0..15

    const int arow  = tid >> 2;        // 0..63
    const int acol4 = (tid & 3) * 4;   // 0,4,8,12
    const int brow  = tid >> 5;        // 0..7
    const int bcol4 = (tid & 31) * 4;  // 0..124

    float acc[8][8];
#pragma unroll
    for (int i = 0; i < 8; i++)
#pragma unroll
        for (int j = 0; j < 8; j++) acc[i][j] = 0.f;

    for (int k0 = 0; k0 < K; k0 += 16) {
#pragma unroll
        for (int i = 0; i < 2; i++) {
            int r = arow + i * 64;
            int gr = by * 128 + r;
            float4 v = make_float4(0.f, 0.f, 0.f, 0.f);
            if (gr < M) v = *(const float4*)&A[(size_t)gr * lda + k0 + acol4];
            As[acol4 + 0][r] = v.x;
            As[acol4 + 1][r] = v.y;
            As[acol4 + 2][r] = v.z;
            As[acol4 + 3][r] = v.w;
        }
#pragma unroll
        for (int i = 0; i < 2; i++) {
            int r = brow + i * 8;
            *(float4*)&Bs[r][bcol4] = *(const float4*)&B[(size_t)(k0 + r) * HD + bx * 128 + bcol4];
        }
        __syncthreads();
#pragma unroll
        for (int k = 0; k < 16; k++) {
            float ra[8], rb[8];
#pragma unroll
            for (int i = 0; i < 8; i++) ra[i] = As[k][tr * 8 + i];
#pragma unroll
            for (int j = 0; j < 8; j++) rb[j] = Bs[k][tc * 8 + j];
#pragma unroll
            for (int i = 0; i < 8; i++)
#pragma unroll
                for (int j = 0; j < 8; j++) acc[i][j] += ra[i] * rb[j];
        }
        __syncthreads();
    }
#pragma unroll
    for (int i = 0; i < 8; i++) {
        int gr = by * 128 + tr * 8 + i;
        if (gr < M) {
#pragma unroll
            for (int j = 0; j < 8; j += 4) {
                *(float4*)&C[(size_t)gr * HD + bx * 128 + tc * 8 + j] =
                    make_float4(acc[i][j], acc[i][j+1], acc[i][j+2], acc[i][j+3]);
            }
        }
    }
}

// ---------------- per-node attention scores ----------------
// es[n,h] = <h[n,h,:], a_src[h,:]>, ed likewise. 1 block/node, 8 warps = 8 heads.
__global__ __launch_bounds__(256)
void attn_score_kernel(const float* __restrict__ hmat,
                       const float* __restrict__ a_src,
                       const float* __restrict__ a_dst,
                       float* __restrict__ es, float* __restrict__ ed) {
    int n = blockIdx.x;
    int w = threadIdx.x >> 5, lane = threadIdx.x & 31;
    float2 hv = *(const float2*)&hmat[(size_t)n * HD + w * DD + lane * 2];
    float2 av = *(const float2*)&a_src[w * DD + lane * 2];
    float2 bv = *(const float2*)&a_dst[w * DD + lane * 2];
    float s = hv.x * av.x + hv.y * av.y;
    float d = hv.x * bv.x + hv.y * bv.y;
#pragma unroll
    for (int o = 16; o; o >>= 1) {
        s += __shfl_down_sync(0xffffffffu, s, o);
        d += __shfl_down_sync(0xffffffffu, d, o);
    }
    if (lane == 0) {
        es[(size_t)n * HH + w] = s;
        ed[(size_t)n * HH + w] = d;
    }
}

// ---------------- fused GAT aggregation (gather, no atomics) ----------------
// 1 block (128 thr) per dst node: segment_max -> exp/denom -> weighted sum -> +bias -> ELU
__global__ __launch_bounds__(128)
void gat_agg_kernel(const float* __restrict__ hmat,
                    const int* __restrict__ csr,
                    const int* __restrict__ rowptr,
                    const float* __restrict__ es,
                    const float* __restrict__ ed,
                    const float* __restrict__ bias,
                    float* __restrict__ out, int ostride) {
    int n = blockIdx.x;
    int t = threadIdx.x;
    int beg = rowptr[n], end = rowptr[n + 1];
    int deg = end - beg;

    __shared__ float edn[8];
    __shared__ float red[16][8];
    __shared__ float mden[16];           // [0..7]=max, [8..15]=1/denom
    __shared__ int   ssh[ECAP];
    __shared__ float esh[ECAP][8];

    if (t < 8) edn[t] = ed[(size_t)n * HH + t];
    for (int j = t; j < deg && j < ECAP; j += 128) ssh[j] = csr[beg + j];
    __syncthreads();

    int hh  = t & 7;
    int l16 = t >> 3;

    // Phase 1: per-head max of leakyrelu(es[src]+ed[n])
    float mx = -INFINITY;
    for (int j = l16; j < deg; j += 16) {
        int s = (j < ECAP) ? ssh[j] : csr[beg + j];
        float e = es[(size_t)s * HH + hh] + edn[hh];
        e = e > 0.f ? e : 0.01f * e;
        if (j < ECAP) esh[j][hh] = e;
        mx = fmaxf(mx, e);
    }
    red[l16][hh] = mx;
    __syncthreads();
    if (t < 8) {
        float v = -INFINITY;
#pragma unroll
        for (int i = 0; i < 16; i++) v = fmaxf(v, red[i][t]);
        mden[t] = v;
    }
    __syncthreads();
    float m_h = mden[hh];

    // Phase 2: denom = sum exp(e - m); cache exp into esh
    float sm = 0.f;
    for (int j = l16; j < deg; j += 16) {
        float e;
        if (j < ECAP) e = esh[j][hh];
        else {
            int s = csr[beg + j];
            e = es[(size_t)s * HH + hh] + edn[hh];
            e = e > 0.f ? e : 0.01f * e;
        }
        float ex = expf(e - m_h);
        if (j < ECAP) esh[j][hh] = ex;
        sm += ex;
    }
    red[l16][hh] = sm;
    __syncthreads();
    if (t < 8) {
        float v = 0.f;
#pragma unroll
        for (int i = 0; i < 16; i++) v += red[i][t];
        mden[8 + t] = 1.f / v;
    }
    __syncthreads();

    // Phase 3: out[n, t*4 .. t*4+3], head = t/16
    int hd = t >> 4;
    float invd = mden[8 + hd];
    float mh2  = mden[hd];
    int col = t * 4;
    float a0 = 0.f, a1 = 0.f, a2 = 0.f, a3 = 0.f;
#pragma unroll 2
    for (int j = 0; j < deg; j++) {
        int s; float ex;
        if (j < ECAP) { s = ssh[j]; ex = esh[j][hd]; }
        else {
            s = csr[beg + j];
            float e = es[(size_t)s * HH + hd] + edn[hd];
            e = e > 0.f ? e : 0.01f * e;
            ex = expf(e - mh2);
        }
        float att = ex * invd;
        float4 hv = *(const float4*)&hmat[(size_t)s * HD + col];
        a0 += hv.x * att; a1 += hv.y * att; a2 += hv.z * att; a3 += hv.w * att;
    }
    float v0 = a0 + bias[col + 0];
    float v1 = a1 + bias[col + 1];
    float v2 = a2 + bias[col + 2];
    float v3 = a3 + bias[col + 3];
    float4 o;
    o.x = v0 > 0.f ? v0 : expm1f(v0);
    o.y = v1 > 0.f ? v1 : expm1f(v1);
    o.z = v2 > 0.f ? v2 : expm1f(v2);
    o.w = v3 > 0.f ? v3 : expm1f(v3);
    *(float4*)&out[(size_t)n * ostride + col] = o;
}

// ---------------- residual: x3 = x0 + x2; also write xc slice ----------------
__global__ void resid_kernel(const float* __restrict__ x0, float* __restrict__ xc,
                             float* __restrict__ x3) {
    int i = blockIdx.x * blockDim.x + threadIdx.x;
    if (i >= NN * HD) return;
    int n = i >> 9, j = i & 511;
    float v = x0[i] + xc[(size_t)n * XCW + 1024 + j];
    x3[i] = v;
    xc[(size_t)n * XCW + 1536 + j] = v;
}

// ---------------- pooling: segment_max over contiguous node ranges ----------------
__global__ void pool_kernel(const float* __restrict__ xc, const int* __restrict__ goff,
                            float* __restrict__ pooled) {
    int g = blockIdx.y;
    int col = blockIdx.x * 128 + threadIdx.x;
    int beg = goff[g], end = goff[g + 1];
    float v = -INFINITY;
    for (int n = beg; n < end; n++)
        v = fmaxf(v, xc[(size_t)n * XCW + col]);
    if (!isfinite(v)) v = 0.f;
    pooled[g * XCW + col] = v;
}

// ---------------- MLP layer 1: z[64,512] = pooled[64,2048] @ mW1 + mb1 ----------------
__global__ __launch_bounds__(128)
void mlp1_kernel(const float* __restrict__ pooled, const float* __restrict__ mW1,
                 const float* __restrict__ mb1, float* __restrict__ z) {
    int j  = blockIdx.x * 128 + threadIdx.x;
    int g0 = blockIdx.y * 8;
    float acc[8];
#pragma unroll
    for (int gg = 0; gg < 8; gg++) acc[gg] = 0.f;
    for (int k = 0; k < XCW; k++) {
        float w = mW1[(size_t)k * HD + j];
#pragma unroll
        for (int gg = 0; gg < 8; gg++)
            acc[gg] += pooled[(g0 + gg) * XCW + k] * w;
    }
    float bb = mb1[j];
#pragma unroll
    for (int gg = 0; gg < 8; gg++)
        z[(g0 + gg) * HD + j] = acc[gg] + bb;
}

// ---------------- BatchNorm (batch stats over 64 rows) + ReLU, in place ----------------
__global__ void bn_relu_kernel(float* __restrict__ z, const float* __restrict__ gamma,
                               const float* __restrict__ beta) {
    int j = blockIdx.x;  // column
    int t = threadIdx.x; // 64 rows
    __shared__ float part[2];
    float v = z[t * HD + j];
    float s = v;
#pragma unroll
    for (int o = 16; o; o >>= 1) s += __shfl_down_sync(0xffffffffu, s, o);
    if ((t & 31) == 0) part[t >> 5] = s;
    __syncthreads();
    float mu = (part[0] + part[1]) * (1.f / 64.f);
    __syncthreads();
    float dv = v - mu;
    float s2 = dv * dv;
#pragma unroll
    for (int o = 16; o; o >>= 1) s2 += __shfl_down_sync(0xffffffffu, s2, o);
    if ((t & 31) == 0) part[t >> 5] = s2;
    __syncthreads();
    float var = (part[0] + part[1]) * (1.f / 64.f);
    float norm = dv * rsqrtf(var + 1e-5f) * gamma[j] + beta[j];
    z[t * HD + j] = fmaxf(norm, 0.f);
}

// ---------------- final GEMM: out[64,10] = relu_z @ mW2 + mb2 ----------------
__global__ void mlp2_kernel(const float* __restrict__ z, const float* __restrict__ mW2,
                            const float* __restrict__ mb2, float* __restrict__ out) {
    int t = threadIdx.x;
    if (t >= GG * CC) return;
    int g = t / CC, c = t % CC;
    float s = mb2[c];
    for (int k = 0; k < HD; k++) s += z[g * HD + k] * mW2[k * CC + c];
    out[t] = s;
}

// ---------------- host: one GAT layer ----------------
static void run_gat(const float* in, int lda, int K,
                    const float* W, const float* a_s, const float* a_d, const float* b,
                    float* pH, float* pES, float* pED,
                    const int* pCSR, const int* pROW,
                    float* outp, int ostride) {
    dim3 ggrid(HD / 128, (NN + 127) / 128);
    sgemm_kernel<<<ggrid, 256>>>(in, lda, W, pH, NN, K);
    attn_score_kernel<<<NN, 256>>>(pH, a_s, a_d, pES, pED);
    gat_agg_kernel<<<NN, 128>>>(pH, pCSR, pROW, pES, pED, b, outp, ostride);
}

extern "C" void kernel_launch(void* const* d_in, const int* in_sizes, int n_in,
                              void* d_out, int out_size) {
    (void)in_sizes; (void)n_in; (void)out_size;
    const float* x     = (const float*)d_in[0];
    const int*   ei    = (const int*)  d_in[1];
    const int*   batch = (const int*)  d_in[2];
    const float* W0  = (const float*)d_in[3];
    const float* as0 = (const float*)d_in[4];
    const float* ad0 = (const float*)d_in[5];
    const float* b0  = (const float*)d_in[6];
    const float* W1  = (const float*)d_in[7];
    const float* as1 = (const float*)d_in[8];
    const float* ad1 = (const float*)d_in[9];
    const float* b1  = (const float*)d_in[10];
    const float* W2  = (const float*)d_in[11];
    const float* as2 = (const float*)d_in[12];
    const float* ad2 = (const float*)d_in[13];
    const float* b2  = (const float*)d_in[14];
    const float* W3  = (const float*)d_in[15];
    const float* as3 = (const float*)d_in[16];
    const float* ad3 = (const float*)d_in[17];
    const float* b3  = (const float*)d_in[18];
    const float* mW1 = (const float*)d_in[19];
    const float* mb1 = (const float*)d_in[20];
    const float* gam = (const float*)d_in[21];
    const float* bet = (const float*)d_in[22];
    const float* mW2 = (const float*)d_in[23];
    const float* mb2 = (const float*)d_in[24];
    float* outp = (float*)d_out;

    const int* src = ei;
    const int* dst = ei + EE;

    float *pH, *pX0, *pX3, *pXC, *pES, *pED, *pPOOL, *pZ;
    int *pCNT, *pCUR, *pROW, *pCSR, *pGOFF;
    cudaGetSymbolAddress((void**)&pH,   g_h);
    cudaGetSymbolAddress((void**)&pX0,  g_x0);
    cudaGetSymbolAddress((void**)&pX3,  g_x3);
    cudaGetSymbolAddress((void**)&pXC,  g_xc);
    cudaGetSymbolAddress((void**)&pES,  g_es);
    cudaGetSymbolAddress((void**)&pED,  g_ed);
    cudaGetSymbolAddress((void**)&pPOOL,g_pool);
    cudaGetSymbolAddress((void**)&pZ,   g_z);
    cudaGetSymbolAddress((void**)&pCNT, g_cnt);
    cudaGetSymbolAddress((void**)&pCUR, g_cur);
    cudaGetSymbolAddress((void**)&pROW, g_rowptr);
    cudaGetSymbolAddress((void**)&pCSR, g_csr);
    cudaGetSymbolAddress((void**)&pGOFF,g_goff);

    // Build dst-CSR (layer-invariant) + graph offsets
    fill_int_kernel<<<(NN + 255) / 256, 256>>>(pCNT, 0, NN);
    hist_kernel<<<(EE + 255) / 256, 256>>>(dst, pCNT);
    scan_kernel<<<1, 1024>>>(pCNT, pROW);
    fill_int_kernel<<<(NN + 255) / 256, 256>>>(pCUR, 0, NN);
    scatter_kernel<<<(EE + 255) / 256, 256>>>(src, dst, pROW, pCUR, pCSR);
    fill_int_kernel<<<1, GG + 1>>>(pGOFF, NN, GG + 1);
    goff_min_kernel<<<(NN + 255) / 256, 256>>>(batch, pGOFF);
    goff_fix_kernel<<<1, 1>>>(pGOFF);

    // GAT stack. xc layout: [xt | x1 | x2 | x3]
    run_gat(x,          FF0,  FF0, W0, as0, ad0, b0, pH, pES, pED, pCSR, pROW, pX0,        HD);
    run_gat(pX0,        HD,   HD,  W1, as1, ad1, b1, pH, pES, pED, pCSR, pROW, pXC + 512,  XCW);
    run_gat(pXC + 512,  XCW,  HD,  W2, as2, ad2, b2, pH, pES, pED, pCSR, pROW, pXC + 1024, XCW);
    resid_kernel<<<(NN * HD + 255) / 256, 256>>>(pX0, pXC, pX3);
    run_gat(pX3,        HD,   HD,  W3, as3, ad3, b3, pH, pES, pED, pCSR, pROW, pXC,        XCW);

    // Pool + MLP head
    pool_kernel<<<dim3(XCW / 128, GG), 128>>>(pXC, pGOFF, pPOOL);
    mlp1_kernel<<<dim3(HD / 128, GG / 8), 128>>>(pPOOL, mW1, mb1, pZ);
    bn_relu_kernel<<<HD, 64>>>(pZ, gam, bet);
    mlp2_kernel<<<1, GG * CC>>>(pZ, mW2, mb2, outp);
}